// round 1
// baseline (speedup 1.0000x reference)
#include <cuda_runtime.h>

// PeakSense: out[b,p] = sum_i exp(-0.5*(mass[b,i]-mu[p])^2 * exp(-lv[p])) * iv[b,i]
// with terms dropped when arg < -10. Masses are sorted per batch -> window search.
//
// B=128, L=4096, N=256. Inputs (metadata order): mu[N], lv[N], masses[B*L],
// intensities[B*L]. Output float [B, N].

#define PS_B 128
#define PS_L 4096
#define PS_N 256
#define THRESH (-10.0f)

__global__ __launch_bounds__(PS_N, 1)
void peaksense_kernel(const float* __restrict__ mu,
                      const float* __restrict__ lv,
                      const float* __restrict__ masses,
                      const float* __restrict__ intens,
                      float* __restrict__ out) {
    __shared__ float sm_mass[PS_L];
    __shared__ float sm_int[PS_L];

    const int b = blockIdx.x;
    const int tid = threadIdx.x;

    // Stage spectrum for this batch into shared (vectorized float4 loads).
    const float4* m4 = reinterpret_cast<const float4*>(masses + (size_t)b * PS_L);
    const float4* i4 = reinterpret_cast<const float4*>(intens + (size_t)b * PS_L);
    float4* sm4 = reinterpret_cast<float4*>(sm_mass);
    float4* si4 = reinterpret_cast<float4*>(sm_int);
    #pragma unroll
    for (int i = tid; i < PS_L / 4; i += PS_N) {
        sm4[i] = m4[i];
        si4[i] = i4[i];
    }
    __syncthreads();

    // One thread per peak.
    const int p = tid;
    const float m = mu[p];
    const float inv_s2 = __expf(-lv[p]);          // 1/sigma^2
    // Window radius: arg >= -10  <=>  d^2 <= 20/inv_s2. Slight inflation so the
    // exact in-loop predicate is the only filter at the boundary.
    const float R = sqrtf(20.0f / inv_s2) * 1.0002f + 1e-5f;
    const float lob = m - R;
    const float hib = m + R;

    // Binary search: first index with sm_mass[idx] >= lob.
    int lo = 0, hi = PS_L;
    while (lo < hi) {
        int mid = (lo + hi) >> 1;
        if (sm_mass[mid] < lob) lo = mid + 1; else hi = mid;
    }

    // Fold -0.5*inv_s2 and log2(e) so the hot loop is: FADD, FMUL, FMUL, cmp, EX2, FFMA.
    const float c_arg = -0.5f * inv_s2;                         // arg = c_arg * d * d
    const float log2e = 1.4426950408889634f;

    float acc = 0.0f;
    for (int i = lo; i < PS_L; ++i) {
        float x = sm_mass[i];
        if (x > hib) break;
        float d = x - m;
        float arg = c_arg * d * d;
        if (arg >= THRESH) {
            acc += exp2f(arg * log2e) * sm_int[i];
        }
    }

    out[(size_t)b * PS_N + p] = acc;
}

extern "C" void kernel_launch(void* const* d_in, const int* in_sizes, int n_in,
                              void* d_out, int out_size) {
    const float* mu     = (const float*)d_in[0];
    const float* lv     = (const float*)d_in[1];
    const float* masses = (const float*)d_in[2];
    const float* intens = (const float*)d_in[3];
    float* out = (float*)d_out;

    peaksense_kernel<<<PS_B, PS_N>>>(mu, lv, masses, intens, out);
}

// round 2
// speedup vs baseline: 1.1604x; 1.1604x over previous
#include <cuda_runtime.h>

// PeakSense: out[b,p] = sum_i exp(-0.5*(mass[b,i]-mu[p])^2 * exp(-lv[p])) * iv[b,i],
// terms with arg < -10 dropped. Masses sorted per batch -> per-peak window.
//
// R2: parallelism. grid (4, B): 64 peaks/block, 4 lanes per peak striding the
// window, no shared staging (input is L2/L1 resident), single lo-search,
// unroll x2 with dual accumulators, shfl reduce.

#define PS_B 128
#define PS_L 4096
#define PS_N 256
#define GROUPS 4                  // blocks per batch
#define PEAKS_PER_BLOCK (PS_N / GROUPS)
#define LANES_PER_PEAK 4
#define THREADS (PEAKS_PER_BLOCK * LANES_PER_PEAK)
#define LOG2E 1.4426950408889634f

__global__ __launch_bounds__(THREADS)
void peaksense_kernel(const float* __restrict__ mu,
                      const float* __restrict__ lv,
                      const float* __restrict__ masses,
                      const float* __restrict__ intens,
                      float* __restrict__ out) {
    const int b   = blockIdx.y;
    const int tid = threadIdx.x;
    const int p   = blockIdx.x * PEAKS_PER_BLOCK + (tid >> 2);
    const int q   = tid & 3;

    const float* __restrict__ mass = masses + (size_t)b * PS_L;
    const float* __restrict__ iv   = intens + (size_t)b * PS_L;

    const float m      = mu[p];
    const float inv_s2 = __expf(-lv[p]);           // 1/sigma^2
    // arg >= -10  <=>  d^2 <= 20/inv_s2. Inflate R slightly so the exact
    // in-loop predicate is the only filter; anything past hib has arg < -10.
    const float R   = sqrtf(20.0f / inv_s2) * 1.0002f + 1e-5f;
    const float lob = m - R;
    const float hib = m + R;

    // Binary search: first index with mass[idx] >= lob. (L2/L1-resident data.)
    int lo = 0, hi = PS_L;
    #pragma unroll 1
    while (lo < hi) {
        int mid = (lo + hi) >> 1;
        if (mass[mid] < lob) lo = mid + 1; else hi = mid;
    }

    // Pre-scale by log2(e): w = exp2(c2*d*d), predicate c2*d*d >= -10*log2e.
    const float c2  = -0.5f * inv_s2 * LOG2E;
    const float th2 = -10.0f * LOG2E;

    float acc0 = 0.0f, acc1 = 0.0f;
    #pragma unroll 1
    for (int i = lo + q; i < PS_L; i += 2 * LANES_PER_PEAK) {
        float x0 = mass[i];
        if (x0 > hib) break;            // all later terms have arg < -10
        int   j  = i + LANES_PER_PEAK;
        bool  jv = (j < PS_L);
        float x1 = jv ? mass[j] : 0.0f;

        float d0 = x0 - m;
        float a0 = c2 * d0 * d0;
        float w0 = (a0 >= th2) ? exp2f(a0) : 0.0f;
        acc0 = fmaf(w0, iv[i], acc0);

        if (jv) {
            float d1 = x1 - m;
            float a1 = c2 * d1 * d1;
            float w1 = (a1 >= th2) ? exp2f(a1) : 0.0f;  // zero past hib too
            acc1 = fmaf(w1, iv[j], acc1);
        }
    }

    // Reduce the 4 lanes of this peak.
    float acc = acc0 + acc1;
    acc += __shfl_xor_sync(0xFFFFFFFF, acc, 1);
    acc += __shfl_xor_sync(0xFFFFFFFF, acc, 2);

    if (q == 0) out[(size_t)b * PS_N + p] = acc;
}

extern "C" void kernel_launch(void* const* d_in, const int* in_sizes, int n_in,
                              void* d_out, int out_size) {
    const float* mu     = (const float*)d_in[0];
    const float* lv     = (const float*)d_in[1];
    const float* masses = (const float*)d_in[2];
    const float* intens = (const float*)d_in[3];
    float* out = (float*)d_out;

    dim3 grid(GROUPS, PS_B);
    peaksense_kernel<<<grid, THREADS>>>(mu, lv, masses, intens, out);
}

// round 3
// speedup vs baseline: 1.3459x; 1.1599x over previous
#include <cuda_runtime.h>

// PeakSense: out[b,p] = sum_i exp(-0.5*(mass[b,i]-mu[p])^2 * exp(-lv[p])) * iv[b,i],
// terms with arg < -10 dropped. Masses sorted per batch -> per-peak window.
//
// R3: latency attack. 8 lanes/peak, 1024 CTAs. Both window bounds found up
// front (lanes 0-3 search lo, 4-7 search hi, shfl broadcast) -> fixed-trip
// main loop with no data-dependent break -> batched loads (MLP), full unroll.

#define PS_B 128
#define PS_L 4096
#define PS_N 256
#define GROUPS 8                          // blocks per batch
#define PEAKS_PER_BLOCK (PS_N / GROUPS)   // 32
#define LANES 8                           // lanes per peak
#define THREADS (PEAKS_PER_BLOCK * LANES) // 256
#define LOG2E 1.4426950408889634f

__global__ __launch_bounds__(THREADS)
void peaksense_kernel(const float* __restrict__ mu,
                      const float* __restrict__ lv,
                      const float* __restrict__ masses,
                      const float* __restrict__ intens,
                      float* __restrict__ out) {
    const int b    = blockIdx.y;
    const int tid  = threadIdx.x;
    const int p    = blockIdx.x * PEAKS_PER_BLOCK + (tid >> 3);
    const int q    = tid & 7;             // lane within peak group
    const int lane = tid & 31;

    const float* __restrict__ mass = masses + (size_t)b * PS_L;
    const float* __restrict__ iv   = intens + (size_t)b * PS_L;

    const float m      = mu[p];
    const float inv_s2 = __expf(-lv[p]);  // 1/sigma^2
    // arg >= -10  <=>  d^2 <= 20/inv_s2. Inflate R slightly so [lo,hi) is a
    // superset of the reference's passing set; the exact in-loop select is
    // the only filter at the boundary.
    const float R   = sqrtf(20.0f / inv_s2) * 1.0002f + 1e-5f;
    const float lob = m - R;
    const float hib = m + R;

    // Cooperative bound search: lanes 0-3 of each peak group find
    // lo = first index with mass >= lob; lanes 4-7 find
    // hi = first index with mass > hib. Redundant x4 within each half (free).
    const float target  = (q < 4) ? lob : hib;
    int slo = 0, shi = PS_L;
    #pragma unroll 1
    while (slo < shi) {
        int mid = (slo + shi) >> 1;
        float v = mass[mid];
        bool goRight = (q < 4) ? (v < target) : (v <= target);
        if (goRight) slo = mid + 1; else shi = mid;
    }
    const int base = lane & ~7;           // first lane of this peak group
    const int lo = __shfl_sync(0xFFFFFFFF, slo, base + 0);
    const int hi = __shfl_sync(0xFFFFFFFF, slo, base + 4);

    // w = exp2(c2*d*d), keep iff c2*d*d >= -10*log2(e).
    const float c2  = -0.5f * inv_s2 * LOG2E;
    const float th2 = -10.0f * LOG2E;

    float acc = 0.0f;
    #pragma unroll 4
    for (int i = lo + q; i < hi; i += LANES) {
        float d = mass[i] - m;
        float a = c2 * d * d;
        float w = (a >= th2) ? exp2f(a) : 0.0f;
        acc = fmaf(w, iv[i], acc);
    }

    // Reduce the 8 lanes of this peak.
    acc += __shfl_xor_sync(0xFFFFFFFF, acc, 1);
    acc += __shfl_xor_sync(0xFFFFFFFF, acc, 2);
    acc += __shfl_xor_sync(0xFFFFFFFF, acc, 4);

    if (q == 0) out[(size_t)b * PS_N + p] = acc;
}

extern "C" void kernel_launch(void* const* d_in, const int* in_sizes, int n_in,
                              void* d_out, int out_size) {
    const float* mu     = (const float*)d_in[0];
    const float* lv     = (const float*)d_in[1];
    const float* masses = (const float*)d_in[2];
    const float* intens = (const float*)d_in[3];
    float* out = (float*)d_out;

    dim3 grid(GROUPS, PS_B);
    peaksense_kernel<<<grid, THREADS>>>(mu, lv, masses, intens, out);
}